// round 1
// baseline (speedup 1.0000x reference)
#include <cuda_runtime.h>

// DeformConv3d, dimension='HW' offsets: t-offset == 0 so sampling is pure 2D
// bilinear at integer t. Shapes fixed by the problem:
//   x:      [2, 16, 8, 64, 64]  fp32
//   temp:   [2, 54, 8, 64, 64]  fp32  (per-tap (off_h, off_w) interleaved)
//   weight: [16, 16, 3, 3, 3]   fp32
//   bias:   [16]                fp32
//   out:    [2, 16, 8, 64, 64]  fp32

#define NB  2
#define NC  16
#define NT  8
#define NH  64
#define NW  64
#define NCO 16
#define NK  27
#define HW  (NH * NW)     // 4096
#define THW (NT * HW)     // 32768

#define TPB 128

// packed dual-fp32 FMA: d = a*b + d  (two fp32 lanes per instruction)
#define FMA2(d, a, b) \
    asm("fma.rn.f32x2 %0, %1, %2, %0;" : "+l"(d) : "l"(a), "l"(b))

__global__ void __launch_bounds__(TPB, 4)
deform_conv3d_hw_kernel(const float* __restrict__ x,
                        const float* __restrict__ temp,
                        const float* __restrict__ wgt,
                        const float* __restrict__ bias,
                        float* __restrict__ out)
{
    // weights transposed to [k][c][co] so the 16 co-values per (k,c) are a
    // contiguous 64B row -> 4x LDS.128 broadcast per inner iteration.
    __shared__ __align__(16) float wsm[NK * NC * NCO];
    for (int i = threadIdx.x; i < NK * NC * NCO; i += TPB) {
        int co = i & 15;
        int c  = (i >> 4) & 15;
        int k  = i >> 8;
        wsm[i] = wgt[(co * NC + c) * NK + k];
    }
    __syncthreads();

    const int gid = blockIdx.x * TPB + threadIdx.x;   // 0 .. 65535
    const int w = gid & 63;
    const int h = (gid >> 6) & 63;
    const int t = (gid >> 12) & 7;
    const int b = gid >> 15;
    const int sp = t * HW + h * NW + w;

    // 16 fp32 accumulators packed into 8 f32x2 registers, seeded with bias.
    unsigned long long acc[8];
#pragma unroll
    for (int j = 0; j < 8; j++) {
        float b0 = bias[2 * j];
        float b1 = bias[2 * j + 1];
        asm("mov.b64 %0, {%1, %2};" : "=l"(acc[j]) : "f"(b0), "f"(b1));
    }

    const float* xb = x + b * (NC * THW);
    const float* tb = temp + b * (2 * NK * THW) + sp;

    int k = 0;
    for (int kt = 0; kt < 3; kt++) {
        const int ti = t - 1 + kt;
        if (ti < 0 || ti >= NT) { k += 9; continue; }   // uniform per warp
        const float* pt = xb + ti * HW;

        for (int kk = 0; kk < 9; kk++, k++) {
            const int kh = kk / 3;
            const int kw = kk - kh * 3;

            const float offh = __ldg(tb + (2 * k) * THW);
            const float offw = __ldg(tb + (2 * k + 1) * THW);

            const float ph = (float)(h - 1 + kh) + offh;
            const float pw = (float)(w - 1 + kw) + offw;

            const int h0 = __float2int_rd(ph);
            const int w0 = __float2int_rd(pw);
            const float fh = ph - (float)h0;
            const float fw = pw - (float)w0;
            const int h1 = h0 + 1;
            const int w1 = w0 + 1;

            const bool vh0 = (h0 >= 0) & (h0 < NH);
            const bool vh1 = (h1 >= 0) & (h1 < NH);
            const bool vw0 = (w0 >= 0) & (w0 < NW);
            const bool vw1 = (w1 >= 0) & (w1 < NW);

            const float gh0 = 1.0f - fh, gw0 = 1.0f - fw;
            const float c00 = (vh0 & vw0) ? gh0 * gw0 : 0.0f;
            const float c01 = (vh0 & vw1) ? gh0 * fw  : 0.0f;
            const float c10 = (vh1 & vw0) ? fh  * gw0 : 0.0f;
            const float c11 = (vh1 & vw1) ? fh  * fw  : 0.0f;

            const int h0c = min(max(h0, 0), NH - 1);
            const int h1c = min(max(h1, 0), NH - 1);
            const int w0c = min(max(w0, 0), NW - 1);
            const int w1c = min(max(w1, 0), NW - 1);

            const int i00 = h0c * NW + w0c;
            const int i01 = h0c * NW + w1c;
            const int i10 = h1c * NW + w0c;
            const int i11 = h1c * NW + w1c;

            const ulonglong2* wr =
                (const ulonglong2*)(wsm + (k * NC) * NCO);

#pragma unroll
            for (int c = 0; c < NC; c++) {
                const float* pc = pt + c * THW;
                float v = c11 * __ldg(pc + i11);
                v = fmaf(c10, __ldg(pc + i10), v);
                v = fmaf(c01, __ldg(pc + i01), v);
                v = fmaf(c00, __ldg(pc + i00), v);

                unsigned long long vv;
                asm("mov.b64 %0, {%1, %1};" : "=l"(vv) : "f"(v));

                const ulonglong2 q0 = wr[c * 4 + 0];
                const ulonglong2 q1 = wr[c * 4 + 1];
                const ulonglong2 q2 = wr[c * 4 + 2];
                const ulonglong2 q3 = wr[c * 4 + 3];
                FMA2(acc[0], vv, q0.x);
                FMA2(acc[1], vv, q0.y);
                FMA2(acc[2], vv, q1.x);
                FMA2(acc[3], vv, q1.y);
                FMA2(acc[4], vv, q2.x);
                FMA2(acc[5], vv, q2.y);
                FMA2(acc[6], vv, q3.x);
                FMA2(acc[7], vv, q3.y);
            }
        }
    }

    float* ob = out + b * (NCO * THW) + sp;
#pragma unroll
    for (int j = 0; j < 8; j++) {
        float r0, r1;
        asm("mov.b64 {%0, %1}, %2;" : "=f"(r0), "=f"(r1) : "l"(acc[j]));
        ob[(2 * j) * THW]     = r0;
        ob[(2 * j + 1) * THW] = r1;
    }
}

extern "C" void kernel_launch(void* const* d_in, const int* in_sizes, int n_in,
                              void* d_out, int out_size)
{
    const float* x    = (const float*)d_in[0];
    const float* temp = (const float*)d_in[1];
    const float* wgt  = (const float*)d_in[2];
    const float* bias = (const float*)d_in[3];
    float* out = (float*)d_out;

    const int total = NB * NT * NH * NW;      // 65536 output points
    deform_conv3d_hw_kernel<<<total / TPB, TPB>>>(x, temp, wgt, bias, out);
}